// round 1
// baseline (speedup 1.0000x reference)
#include <cuda_runtime.h>
#include <math.h>

#define N_ATOMS 2048
#define NG 8
#define NE 4
#define NPERM 10
#define NACC 352          // 32 G-features + 320 M-features (before squares)
#define PI_F 3.14159265358979323846f
#define RC_F 6.0f
#define RCA_F 4.0f

// scratch: per-atom feature accumulators (G at [0,32), M at [32,352))
__device__ float g_feat[N_ATOMS * NACC];

// -------------------------------------------------------------------------
// Kernel 1: per-atom descriptor accumulation with deterministic neighbor
// compaction.  One block = one atom i, 128 threads.
// Shared record layout per survivor (stride 32 floats):
//   [0:8)   rad_a (angular basis, zero if r > rc_ang)
//   [8:18)  ang monomials [1, uz, uy, ux, uz2, uyuz, uy2, uxuz, uxuy, ux2]
//   [18:26) rad (radial basis)
//   [26:30) spec_ij
//   [30]    1.0f  (so G-accumulators use the same 3-operand FMA form)
// -------------------------------------------------------------------------
__global__ __launch_bounds__(128) void feat_kernel(
    const float* __restrict__ pos,
    const float* __restrict__ spec,
    const float* __restrict__ kn_rad,
    const float* __restrict__ kn_ang,
    const float* __restrict__ rbf_w,
    const float* __restrict__ rbf_b,
    const float* __restrict__ rbf_aw,
    const float* __restrict__ rbf_ab,
    int N)
{
    const int i    = blockIdx.x;
    const int tid  = threadIdx.x;
    const int lane = tid & 31;
    const int w    = tid >> 5;

    __shared__ float buf[128][32];
    __shared__ int   warpcnt[4];
    __shared__ float crk[8], cak[8], wr[8], br[8], wa[8], ba[8];

    if (tid < 8) {
        crk[tid] = (PI_F / RC_F)  * (float)(tid + 1) * kn_rad[tid];
        cak[tid] = (PI_F / RCA_F) * (float)(tid + 1) * kn_ang[tid];
        wr[tid]  = rbf_w[tid];  br[tid] = rbf_b[tid];
        wa[tid]  = rbf_aw[tid]; ba[tid] = rbf_ab[tid];
    }

    const float pix = pos[3 * i + 0];
    const float piy = pos[3 * i + 1];
    const float piz = pos[3 * i + 2];
    const float si0 = spec[i * NE + 0];
    const float si1 = spec[i * NE + 1];
    const float si2 = spec[i * NE + 2];
    const float si3 = spec[i * NE + 3];

    // decode this thread's (up to 3) accumulators: a = tid, tid+128, tid+256
    int o1[3], o2[3], o3[3], fidx[3];
    #pragma unroll
    for (int k = 0; k < 3; k++) {
        int a = tid + k * 128;
        if (a < NACC) {
            int pe = a >> 3;
            int l  = a & 7;
            if (pe < 40) {            // M accumulator
                int p = pe >> 2;
                int e = pe & 3;
                o1[k] = l;            // rad_a[l]
                o2[k] = 8 + p;        // ang[p]
                o3[k] = 26 + e;       // spec[e]
                fidx[k] = 32 + l * (NPERM * NE) + p * NE + e;
            } else {                  // G accumulator
                int e = pe - 40;
                o1[k] = 18 + l;       // rad[l]
                o2[k] = 26 + e;       // spec[e]
                o3[k] = 30;           // 1.0f
                fidx[k] = l * NE + e;
            }
        }
    }
    const bool has2 = true;           // tid+128 <= 255 < 352 always
    const bool has3 = (tid + 256) < NACC;   // tid < 96

    float acc0 = 0.0f, acc1 = 0.0f, acc2 = 0.0f;

    for (int tile = 0; tile < N; tile += 128) {
        int  j = tile + tid;
        int  pred = 0;
        float rx = 0.f, ry = 0.f, rz = 0.f, rn = 1.0f;
        if (j < N) {
            rx = pix - pos[3 * j + 0];
            ry = piy - pos[3 * j + 1];
            rz = piz - pos[3 * j + 2];
            float d2 = rx * rx + ry * ry + rz * rz + 1e-16f;
            rn = sqrtf(d2);
            pred = (rn <= RC_F) && (rn > 1e-8f);
        }
        unsigned m = __ballot_sync(0xffffffffu, pred);
        if (lane == 0) warpcnt[w] = __popc(m);
        __syncthreads();

        int base = 0;
        #pragma unroll
        for (int k = 0; k < 4; k++) if (k < w) base += warpcnt[k];
        int cnt = warpcnt[0] + warpcnt[1] + warpcnt[2] + warpcnt[3];

        if (pred) {
            int slot = base + __popc(m & ((1u << lane) - 1u));
            float* rec = &buf[slot][0];
            float inv_r = 1.0f / rn;

            // species products
            rec[26] = si0 * spec[j * NE + 0];
            rec[27] = si1 * spec[j * NE + 1];
            rec[28] = si2 * spec[j * NE + 2];
            rec[29] = si3 * spec[j * NE + 3];
            rec[30] = 1.0f;

            bool  in_ang = (rn <= RCA_F);
            float fc  = 0.5f * (cosf((PI_F / RC_F)  * fminf(rn, RC_F)) + 1.0f);
            float fca = in_ang ? 0.5f * (cosf((PI_F / RCA_F) * rn) + 1.0f) : 0.0f;

            #pragma unroll
            for (int n = 0; n < NG; n++) {
                float gate  = 1.0f / (1.0f + expf(-(rn * wr[n] + br[n])));
                rec[18 + n] = sinf(crk[n] * rn) * inv_r * fc * gate;
                float gatea = 1.0f / (1.0f + expf(-(rn * wa[n] + ba[n])));
                rec[n] = in_ang ? (sinf(cak[n] * rn) * inv_r * fca * gatea) : 0.0f;
            }

            float ux = rx * inv_r, uy = ry * inv_r, uz = rz * inv_r;
            rec[8]  = 1.0f;
            rec[9]  = uz;
            rec[10] = uy;
            rec[11] = ux;
            rec[12] = uz * uz;
            rec[13] = uy * uz;
            rec[14] = uy * uy;
            rec[15] = ux * uz;
            rec[16] = ux * uy;
            rec[17] = ux * ux;
        }
        __syncthreads();

        // accumulate over compacted survivors (cnt is uniform across block)
        #pragma unroll 2
        for (int s = 0; s < cnt; s++) {
            const float* rec = &buf[s][0];
            acc0 += rec[o1[0]] * rec[o2[0]] * rec[o3[0]];
            acc1 += rec[o1[1]] * rec[o2[1]] * rec[o3[1]];
            if (has3) acc2 += rec[o1[2]] * rec[o2[2]] * rec[o3[2]];
        }
        // next tile's buf writes are gated by the __syncthreads after the
        // ballot, which can only be passed once all threads finished this
        // accumulate loop -> no extra barrier needed here.
    }

    g_feat[i * NACC + fidx[0]] = acc0;
    if (has2) g_feat[i * NACC + fidx[1]] = acc1;
    if (has3) g_feat[i * NACC + fidx[2]] = acc2;
}

// -------------------------------------------------------------------------
// Kernel 2: per-atom MLP  (672 -> 64 tanh -> 64 tanh -> 1)
// feat[f] : f <  352 -> g_feat[i][f]
//           f >= 352 -> g_feat[i][f-320]^2   (M*M block, offset 352-32=320)
// One block = one atom, 64 threads (one per hidden unit).
// -------------------------------------------------------------------------
__global__ __launch_bounds__(64) void mlp_kernel(
    const float* __restrict__ W1, const float* __restrict__ b1,
    const float* __restrict__ W2, const float* __restrict__ b2,
    const float* __restrict__ W3, const float* __restrict__ b3,
    float* __restrict__ out, int N)
{
    const int i = blockIdx.x;
    const int h = threadIdx.x;

    __shared__ float sf[NACC];
    __shared__ float sh1[64];
    __shared__ float part[2];

    for (int f = h; f < NACC; f += 64) sf[f] = g_feat[i * NACC + f];
    __syncthreads();

    float s = b1[h];
    #pragma unroll 8
    for (int f = 0; f < NACC; f++)
        s += sf[f] * W1[f * 64 + h];
    #pragma unroll 8
    for (int f = NACC; f < 2 * 320 + 32; f++) {
        float v = sf[f - 320];
        s += (v * v) * W1[f * 64 + h];
    }
    sh1[h] = tanhf(s);
    __syncthreads();

    float s2 = b2[h];
    #pragma unroll 8
    for (int k = 0; k < 64; k++)
        s2 += sh1[k] * W2[k * 64 + h];
    float contrib = tanhf(s2) * W3[h];

    #pragma unroll
    for (int o = 16; o > 0; o >>= 1)
        contrib += __shfl_down_sync(0xffffffffu, contrib, o);
    if ((h & 31) == 0) part[h >> 5] = contrib;
    __syncthreads();
    if (h == 0) out[i] = part[0] + part[1] + b3[0];
}

// -------------------------------------------------------------------------
extern "C" void kernel_launch(void* const* d_in, const int* in_sizes, int n_in,
                              void* d_out, int out_size)
{
    const float* pos    = (const float*)d_in[0];
    const float* spec   = (const float*)d_in[1];
    const float* kn_rad = (const float*)d_in[2];
    const float* kn_ang = (const float*)d_in[3];
    const float* rbf_w  = (const float*)d_in[4];
    const float* rbf_b  = (const float*)d_in[5];
    const float* rbf_aw = (const float*)d_in[6];
    const float* rbf_ab = (const float*)d_in[7];
    const float* W1     = (const float*)d_in[8];
    const float* b1     = (const float*)d_in[9];
    const float* W2     = (const float*)d_in[10];
    const float* b2     = (const float*)d_in[11];
    const float* W3     = (const float*)d_in[12];
    const float* b3     = (const float*)d_in[13];

    int N = in_sizes[0] / 3;   // 2048

    feat_kernel<<<N, 128>>>(pos, spec, kn_rad, kn_ang,
                            rbf_w, rbf_b, rbf_aw, rbf_ab, N);
    mlp_kernel<<<N, 64>>>(W1, b1, W2, b2, W3, b3, (float*)d_out, N);
}

// round 2
// speedup vs baseline: 1.9195x; 1.9195x over previous
#include <cuda_runtime.h>
#include <math.h>

#define N_ATOMS 2048
#define NG 8
#define NE 4
#define NPERM 10
#define NACC 352          // 32 G-features + 320 M-features (before squares)
#define NFEAT 672
#define PI_F 3.14159265358979323846f
#define RC_F 6.0f
#define RCA_F 4.0f

// scratch: per-atom feature accumulators (G at [0,32), M at [32,352))
__device__ float g_feat[N_ATOMS * NACC];

__device__ __forceinline__ float fast_tanh(float x) {
    float y;
    asm("tanh.approx.f32 %0, %1;" : "=f"(y) : "f"(x));
    return y;
}
__device__ __forceinline__ float fast_sigmoid(float x) {
    return 0.5f * fast_tanh(0.5f * x) + 0.5f;
}

// -------------------------------------------------------------------------
// Kernel 1: per-atom descriptor accumulation with deterministic neighbor
// compaction.  One block = one atom i, 128 threads.
// Shared record layout per survivor (stride 32 floats):
//   [0:8)   rad_a   [8:18) ang   [18:26) rad   [26:30) spec_ij   [30] 1.0f
// -------------------------------------------------------------------------
__global__ __launch_bounds__(128) void feat_kernel(
    const float* __restrict__ pos,
    const float* __restrict__ spec,
    const float* __restrict__ kn_rad,
    const float* __restrict__ kn_ang,
    const float* __restrict__ rbf_w,
    const float* __restrict__ rbf_b,
    const float* __restrict__ rbf_aw,
    const float* __restrict__ rbf_ab,
    int N)
{
    const int i    = blockIdx.x;
    const int tid  = threadIdx.x;
    const int lane = tid & 31;
    const int w    = tid >> 5;

    __shared__ float buf[128][32];
    __shared__ int   warpcnt[4];
    __shared__ float crk[8], cak[8], wr[8], br[8], wa[8], ba[8];

    if (tid < 8) {
        crk[tid] = (PI_F / RC_F)  * (float)(tid + 1) * kn_rad[tid];
        cak[tid] = (PI_F / RCA_F) * (float)(tid + 1) * kn_ang[tid];
        wr[tid]  = rbf_w[tid];  br[tid] = rbf_b[tid];
        wa[tid]  = rbf_aw[tid]; ba[tid] = rbf_ab[tid];
    }

    const float pix = pos[3 * i + 0];
    const float piy = pos[3 * i + 1];
    const float piz = pos[3 * i + 2];
    const float si0 = spec[i * NE + 0];
    const float si1 = spec[i * NE + 1];
    const float si2 = spec[i * NE + 2];
    const float si3 = spec[i * NE + 3];

    // decode this thread's (up to 3) accumulators: a = tid, tid+128, tid+256
    int o1[3], o2[3], o3[3], fidx[3];
    #pragma unroll
    for (int k = 0; k < 3; k++) {
        int a = tid + k * 128;
        if (a < NACC) {
            int pe = a >> 3;
            int l  = a & 7;
            if (pe < 40) {            // M accumulator
                int p = pe >> 2;
                int e = pe & 3;
                o1[k] = l;            // rad_a[l]
                o2[k] = 8 + p;        // ang[p]
                o3[k] = 26 + e;       // spec[e]
                fidx[k] = 32 + l * (NPERM * NE) + p * NE + e;
            } else {                  // G accumulator
                int e = pe - 40;
                o1[k] = 18 + l;       // rad[l]
                o2[k] = 26 + e;       // spec[e]
                o3[k] = 30;           // 1.0f
                fidx[k] = l * NE + e;
            }
        }
    }
    const bool has3 = (tid + 256) < NACC;   // tid < 96

    float acc0 = 0.0f, acc1 = 0.0f, acc2 = 0.0f;

    for (int tile = 0; tile < N; tile += 128) {
        int  j = tile + tid;
        int  pred = 0;
        float rx = 0.f, ry = 0.f, rz = 0.f, rn = 1.0f, inv_r = 1.0f;
        if (j < N) {
            rx = pix - pos[3 * j + 0];
            ry = piy - pos[3 * j + 1];
            rz = piz - pos[3 * j + 2];
            float d2 = rx * rx + ry * ry + rz * rz + 1e-16f;
            inv_r = rsqrtf(d2);
            rn = d2 * inv_r;
            pred = (j != i) && (rn <= RC_F);
        }
        unsigned m = __ballot_sync(0xffffffffu, pred);
        if (lane == 0) warpcnt[w] = __popc(m);
        __syncthreads();

        int base = 0;
        #pragma unroll
        for (int k = 0; k < 4; k++) if (k < w) base += warpcnt[k];
        int cnt = warpcnt[0] + warpcnt[1] + warpcnt[2] + warpcnt[3];

        if (pred) {
            int slot = base + __popc(m & ((1u << lane) - 1u));
            float* rec = &buf[slot][0];

            rec[26] = si0 * spec[j * NE + 0];
            rec[27] = si1 * spec[j * NE + 1];
            rec[28] = si2 * spec[j * NE + 2];
            rec[29] = si3 * spec[j * NE + 3];
            rec[30] = 1.0f;

            bool  in_ang = (rn <= RCA_F);
            float fc  = 0.5f * (__cosf((PI_F / RC_F)  * rn) + 1.0f);
            float fca = in_ang ? 0.5f * (__cosf((PI_F / RCA_F) * rn) + 1.0f) : 0.0f;
            float sr = inv_r * fc;
            float sa = inv_r * fca;   // 0 when outside angular cutoff

            #pragma unroll
            for (int n = 0; n < NG; n++) {
                rec[18 + n] = __sinf(crk[n] * rn) * sr * fast_sigmoid(rn * wr[n] + br[n]);
                rec[n]      = in_ang
                            ? (__sinf(cak[n] * rn) * sa * fast_sigmoid(rn * wa[n] + ba[n]))
                            : 0.0f;
            }

            float ux = rx * inv_r, uy = ry * inv_r, uz = rz * inv_r;
            rec[8]  = 1.0f;
            rec[9]  = uz;
            rec[10] = uy;
            rec[11] = ux;
            rec[12] = uz * uz;
            rec[13] = uy * uz;
            rec[14] = uy * uy;
            rec[15] = ux * uz;
            rec[16] = ux * uy;
            rec[17] = ux * ux;
        }
        __syncthreads();

        // accumulate over compacted survivors (cnt uniform across block)
        #pragma unroll 4
        for (int s = 0; s < cnt; s++) {
            const float* rec = &buf[s][0];
            acc0 += rec[o1[0]] * rec[o2[0]] * rec[o3[0]];
            acc1 += rec[o1[1]] * rec[o2[1]] * rec[o3[1]];
            if (has3) acc2 += rec[o1[2]] * rec[o2[2]] * rec[o3[2]];
        }
        // the __syncthreads after next tile's ballot gates buf reuse
    }

    g_feat[i * NACC + fidx[0]] = acc0;
    g_feat[i * NACC + fidx[1]] = acc1;
    if (has3) g_feat[i * NACC + fidx[2]] = acc2;
}

// -------------------------------------------------------------------------
// Kernel 2: per-atom MLP (672 -> 64 tanh -> 64 tanh -> 1), 8 atoms / block.
// 256 threads = 4 f-slices x 64 hidden units.  W1 row loaded once per block
// and reused across 8 atoms (8x less L1/L2 weight traffic than 1 atom/blk).
// -------------------------------------------------------------------------
#define ATOMS 8
__global__ __launch_bounds__(256) void mlp_kernel(
    const float* __restrict__ W1, const float* __restrict__ b1,
    const float* __restrict__ W2, const float* __restrict__ b2,
    const float* __restrict__ W3, const float* __restrict__ b3,
    float* __restrict__ out, int N)
{
    const int i0    = blockIdx.x * ATOMS;
    const int tid   = threadIdx.x;
    const int slice = tid >> 6;    // 0..3
    const int h     = tid & 63;
    const int lane  = tid & 31;

    __shared__ float sf[NFEAT * ATOMS];       // [f][a]  21.5 KB
    __shared__ float part1[4 * 64 * ATOMS];   // [slice][h][a]  8 KB
    __shared__ float sh1[64 * ATOMS];         // [k][a]  2 KB

    // load raw 352 features per atom (coalesced over f)
    for (int idx = tid; idx < NACC * ATOMS; idx += 256) {
        int a = idx / NACC;
        int f = idx - a * NACC;
        sf[f * ATOMS + a] = g_feat[(i0 + a) * NACC + f];
    }
    __syncthreads();
    // squared M block: features [352,672) = sf[f-320]^2
    for (int idx = tid; idx < 320 * ATOMS; idx += 256) {
        int a = idx & 7;
        int q = idx >> 3;                 // 0..319
        float v = sf[(32 + q) * ATOMS + a];
        sf[(352 + q) * ATOMS + a] = v * v;
    }
    __syncthreads();

    // ---- layer 1: each slice handles 168 of the 672 features ----
    float acc[ATOMS];
    #pragma unroll
    for (int a = 0; a < ATOMS; a++) acc[a] = 0.0f;

    const int f0 = slice * 168;
    #pragma unroll 4
    for (int f = f0; f < f0 + 168; f++) {
        float w1 = W1[f * 64 + h];
        float4 v0 = *(const float4*)&sf[f * ATOMS];
        float4 v1 = *(const float4*)&sf[f * ATOMS + 4];
        acc[0] += v0.x * w1;  acc[1] += v0.y * w1;
        acc[2] += v0.z * w1;  acc[3] += v0.w * w1;
        acc[4] += v1.x * w1;  acc[5] += v1.y * w1;
        acc[6] += v1.z * w1;  acc[7] += v1.w * w1;
    }
    #pragma unroll
    for (int a = 0; a < ATOMS; a++)
        part1[(slice * 64 + h) * ATOMS + a] = acc[a];
    __syncthreads();

    if (slice == 0) {
        float bb = b1[h];
        #pragma unroll
        for (int a = 0; a < ATOMS; a++) {
            float s = acc[a]
                    + part1[(64  + h) * ATOMS + a]
                    + part1[(128 + h) * ATOMS + a]
                    + part1[(192 + h) * ATOMS + a];
            sh1[h * ATOMS + a] = fast_tanh(s + bb);
        }
    }
    __syncthreads();

    if (slice == 0) {
        // ---- layer 2 + 3 on first 64 threads ----
        float a2[ATOMS];
        float b2h = b2[h];
        #pragma unroll
        for (int a = 0; a < ATOMS; a++) a2[a] = b2h;
        #pragma unroll 4
        for (int k = 0; k < 64; k++) {
            float w2 = W2[k * 64 + h];
            float4 v0 = *(const float4*)&sh1[k * ATOMS];
            float4 v1 = *(const float4*)&sh1[k * ATOMS + 4];
            a2[0] += v0.x * w2;  a2[1] += v0.y * w2;
            a2[2] += v0.z * w2;  a2[3] += v0.w * w2;
            a2[4] += v1.x * w2;  a2[5] += v1.y * w2;
            a2[6] += v1.z * w2;  a2[7] += v1.w * w2;
        }
        float w3 = W3[h];
        float c[ATOMS];
        #pragma unroll
        for (int a = 0; a < ATOMS; a++) c[a] = fast_tanh(a2[a]) * w3;

        #pragma unroll
        for (int o = 16; o > 0; o >>= 1) {
            #pragma unroll
            for (int a = 0; a < ATOMS; a++)
                c[a] += __shfl_down_sync(0xffffffffu, c[a], o);
        }
        if (lane == 0) {
            int wwarp = h >> 5;   // 0 or 1
            #pragma unroll
            for (int a = 0; a < ATOMS; a++)
                part1[wwarp * ATOMS + a] = c[a];
        }
    }
    __syncthreads();
    if (tid < ATOMS)
        out[i0 + tid] = part1[tid] + part1[ATOMS + tid] + b3[0];
}

// -------------------------------------------------------------------------
extern "C" void kernel_launch(void* const* d_in, const int* in_sizes, int n_in,
                              void* d_out, int out_size)
{
    const float* pos    = (const float*)d_in[0];
    const float* spec   = (const float*)d_in[1];
    const float* kn_rad = (const float*)d_in[2];
    const float* kn_ang = (const float*)d_in[3];
    const float* rbf_w  = (const float*)d_in[4];
    const float* rbf_b  = (const float*)d_in[5];
    const float* rbf_aw = (const float*)d_in[6];
    const float* rbf_ab = (const float*)d_in[7];
    const float* W1     = (const float*)d_in[8];
    const float* b1     = (const float*)d_in[9];
    const float* W2     = (const float*)d_in[10];
    const float* b2     = (const float*)d_in[11];
    const float* W3     = (const float*)d_in[12];
    const float* b3     = (const float*)d_in[13];

    int N = in_sizes[0] / 3;   // 2048

    feat_kernel<<<N, 128>>>(pos, spec, kn_rad, kn_ang,
                            rbf_w, rbf_b, rbf_aw, rbf_ab, N);
    mlp_kernel<<<N / ATOMS, 256>>>(W1, b1, W2, b2, W3, b3, (float*)d_out, N);
}

// round 3
// speedup vs baseline: 2.1898x; 1.1409x over previous
#include <cuda_runtime.h>
#include <math.h>

#define NG 8
#define NE 4
#define NPERM 10
#define NACC 352          // 32 G + 320 M (before squares)
#define PI_F 3.14159265358979323846f
#define RC_F 6.0f
#define RCA_F 4.0f

// scratch: per-atom feature accumulators (G at [0,32), M at [32,352))
__device__ float g_feat[2048 * NACC];

__device__ __forceinline__ float fast_tanh(float x) {
    float y;
    asm("tanh.approx.f32 %0, %1;" : "=f"(y) : "f"(x));
    return y;
}
__device__ __forceinline__ float fast_sigmoid(float x) {
    return 0.5f * fast_tanh(0.5f * x) + 0.5f;
}

// -------------------------------------------------------------------------
// Kernel 1: descriptors.  One block = one atom i, 128 threads.
// TWO deterministic compactions per 128-j tile:
//   radial  (r<=6):  rbuf rec stride 12: rad[8] @0, spec[4] @8
//   angular (r<=4):  abuf rec stride 24: rad_a[8] @0, ang[10] @8, spec[4] @18
// 320 M-accumulators sweep only the angular list (~30% of radial count).
// -------------------------------------------------------------------------
__global__ __launch_bounds__(128) void feat_kernel(
    const float* __restrict__ pos,
    const float* __restrict__ spec,
    const float* __restrict__ kn_rad,
    const float* __restrict__ kn_ang,
    const float* __restrict__ rbf_w,
    const float* __restrict__ rbf_b,
    const float* __restrict__ rbf_aw,
    const float* __restrict__ rbf_ab,
    int N)
{
    const int i    = blockIdx.x;
    const int tid  = threadIdx.x;
    const int lane = tid & 31;
    const int w    = tid >> 5;

    __shared__ float rbuf[128 * 12];
    __shared__ float abuf[128 * 24];
    __shared__ int   wc_r[4], wc_a[4];
    __shared__ float crk[8], cak[8], wr[8], br[8], wa[8], ba[8];

    if (tid < 8) {
        crk[tid] = (PI_F / RC_F)  * (float)(tid + 1) * kn_rad[tid];
        cak[tid] = (PI_F / RCA_F) * (float)(tid + 1) * kn_ang[tid];
        wr[tid]  = rbf_w[tid];  br[tid] = rbf_b[tid];
        wa[tid]  = rbf_aw[tid]; ba[tid] = rbf_ab[tid];
    }

    const float pix = pos[3 * i + 0];
    const float piy = pos[3 * i + 1];
    const float piz = pos[3 * i + 2];
    const float4 si = ((const float4*)spec)[i];

    // ---- M-accumulator decode: a = l*40 + p*4 + e ----
    int oa[3], ob[3], oc[3], fm[3];
    #pragma unroll
    for (int k = 0; k < 3; k++) {
        int a = tid + k * 128;
        if (a < 320) {
            int l = a / 40;
            int r = a - l * 40;
            int p = r >> 2;
            int e = r & 3;
            oa[k] = l;
            ob[k] = 8 + p;
            oc[k] = 18 + e;
            fm[k] = 32 + a;
        }
    }
    const bool has2 = (tid < 64);      // a2 = tid+256 < 320
    // ---- G accumulator: threads 96..127, one each ----
    const bool hasG = (tid >= 96);
    const int  gidx = tid - 96;        // l = gidx>>2, e = gidx&3
    const int  gl   = gidx >> 2;
    const int  ge   = 8 + (gidx & 3);

    float acc0 = 0.0f, acc1 = 0.0f, acc2 = 0.0f, gacc = 0.0f;

    for (int tile = 0; tile < N; tile += 128) {
        int  j = tile + tid;
        int  pr = 0, pa = 0;
        float rx = 0.f, ry = 0.f, rz = 0.f, rn = 1.0f, inv_r = 1.0f;
        if (j < N) {
            rx = pix - pos[3 * j + 0];
            ry = piy - pos[3 * j + 1];
            rz = piz - pos[3 * j + 2];
            float d2 = rx * rx + ry * ry + rz * rz + 1e-16f;
            inv_r = rsqrtf(d2);
            rn = d2 * inv_r;
            pr = (j != i) && (rn <= RC_F);
            pa = (j != i) && (rn <= RCA_F);
        }
        unsigned mr = __ballot_sync(0xffffffffu, pr);
        unsigned ma = __ballot_sync(0xffffffffu, pa);
        if (lane == 0) { wc_r[w] = __popc(mr); wc_a[w] = __popc(ma); }
        __syncthreads();

        int base_r = 0, base_a = 0;
        #pragma unroll
        for (int k = 0; k < 4; k++) {
            if (k < w) { base_r += wc_r[k]; base_a += wc_a[k]; }
        }
        int cnt_r = wc_r[0] + wc_r[1] + wc_r[2] + wc_r[3];
        int cnt_a = wc_a[0] + wc_a[1] + wc_a[2] + wc_a[3];

        if (pr) {
            float4 sj = ((const float4*)spec)[j];
            float s0 = si.x * sj.x, s1 = si.y * sj.y;
            float s2 = si.z * sj.z, s3 = si.w * sj.w;

            // radial record
            {
                int slot = base_r + __popc(mr & ((1u << lane) - 1u));
                float* rec = &rbuf[slot * 12];
                float fc = 0.5f * (__cosf((PI_F / RC_F) * rn) + 1.0f);
                float sr = inv_r * fc;
                #pragma unroll
                for (int n = 0; n < NG; n++)
                    rec[n] = __sinf(crk[n] * rn) * sr
                           * fast_sigmoid(rn * wr[n] + br[n]);
                rec[8]  = s0; rec[9] = s1; rec[10] = s2; rec[11] = s3;
            }
            // angular record (subset)
            if (pa) {
                int slot = base_a + __popc(ma & ((1u << lane) - 1u));
                float* rec = &abuf[slot * 24];
                float fca = 0.5f * (__cosf((PI_F / RCA_F) * rn) + 1.0f);
                float sa = inv_r * fca;
                #pragma unroll
                for (int n = 0; n < NG; n++)
                    rec[n] = __sinf(cak[n] * rn) * sa
                           * fast_sigmoid(rn * wa[n] + ba[n]);
                float ux = rx * inv_r, uy = ry * inv_r, uz = rz * inv_r;
                rec[8]  = 1.0f;
                rec[9]  = uz;
                rec[10] = uy;
                rec[11] = ux;
                rec[12] = uz * uz;
                rec[13] = uy * uz;
                rec[14] = uy * uy;
                rec[15] = ux * uz;
                rec[16] = ux * uy;
                rec[17] = ux * ux;
                rec[18] = s0; rec[19] = s1; rec[20] = s2; rec[21] = s3;
            }
        }
        __syncthreads();

        // ---- M accumulation over angular survivors ----
        #pragma unroll 2
        for (int s = 0; s < cnt_a; s++) {
            const float* rec = &abuf[s * 24];
            acc0 += rec[oa[0]] * rec[ob[0]] * rec[oc[0]];
            acc1 += rec[oa[1]] * rec[ob[1]] * rec[oc[1]];
            if (has2) acc2 += rec[oa[2]] * rec[ob[2]] * rec[oc[2]];
        }
        // ---- G accumulation over radial survivors (warp 3 only) ----
        if (hasG) {
            #pragma unroll 4
            for (int s = 0; s < cnt_r; s++) {
                const float* rec = &rbuf[s * 12];
                gacc = fmaf(rec[gl], rec[ge], gacc);
            }
        }
        // next tile's shared writes are gated by its post-ballot barrier
    }

    float* fo = &g_feat[i * NACC];
    fo[fm[0]] = acc0;
    fo[fm[1]] = acc1;
    if (has2) fo[fm[2]] = acc2;
    if (hasG) fo[gidx]  = gacc;
}

// -------------------------------------------------------------------------
// Kernel 2: per-atom MLP (672 -> 64 tanh -> 64 tanh -> 1), 16 atoms/block.
// 256 threads: h = tid&63 (hidden unit), grp = tid>>6 (4 atoms each).
// Square-features computed inline (no 672-wide staging).
// -------------------------------------------------------------------------
#define ATOMS 16
#define SFS 20            // sf row stride (floats); %4==0 for LDS.128 align
__global__ __launch_bounds__(256) void mlp_kernel(
    const float* __restrict__ W1, const float* __restrict__ b1,
    const float* __restrict__ W2, const float* __restrict__ b2,
    const float* __restrict__ W3, const float* __restrict__ b3,
    float* __restrict__ out, int N)
{
    const int i0   = blockIdx.x * ATOMS;
    const int tid  = threadIdx.x;
    const int h    = tid & 63;
    const int grp  = tid >> 6;          // 0..3 -> atoms 4*grp..4*grp+3
    const int half = (tid >> 5) & 1;

    __shared__ float sf[NACC * SFS];    // [f][atom], 28.2 KB
    __shared__ float sh1[64 * 16];      // [k][atom]
    __shared__ float part[8 * 4];       // [grp*2+half][local atom]

    for (int idx = tid; idx < NACC * ATOMS; idx += 256) {
        int a = idx / NACC;
        int f = idx - a * NACC;
        sf[f * SFS + a] = g_feat[(i0 + a) * NACC + f];
    }
    __syncthreads();

    // ---- layer 1 ----
    float acc[4] = {0.f, 0.f, 0.f, 0.f};
    // G block: f in [0,32) (no squared counterpart)
    #pragma unroll 8
    for (int f = 0; f < 32; f++) {
        float w = W1[f * 64 + h];
        float4 v = *(const float4*)&sf[f * SFS + grp * 4];
        acc[0] += v.x * w; acc[1] += v.y * w;
        acc[2] += v.z * w; acc[3] += v.w * w;
    }
    // M block: f in [32,352) feeds both W1[f] and W1[f+320] (squared)
    #pragma unroll 8
    for (int f = 32; f < NACC; f++) {
        float w  = W1[f * 64 + h];
        float w2 = W1[(f + 320) * 64 + h];
        float4 v = *(const float4*)&sf[f * SFS + grp * 4];
        acc[0] += v.x * w; acc[1] += v.y * w;
        acc[2] += v.z * w; acc[3] += v.w * w;
        acc[0] += (v.x * v.x) * w2; acc[1] += (v.y * v.y) * w2;
        acc[2] += (v.z * v.z) * w2; acc[3] += (v.w * v.w) * w2;
    }
    {
        float bb = b1[h];
        #pragma unroll
        for (int aa = 0; aa < 4; aa++)
            sh1[h * 16 + grp * 4 + aa] = fast_tanh(acc[aa] + bb);
    }
    __syncthreads();

    // ---- layer 2 ----
    float a2[4];
    {
        float bb = b2[h];
        a2[0] = bb; a2[1] = bb; a2[2] = bb; a2[3] = bb;
    }
    #pragma unroll 8
    for (int k = 0; k < 64; k++) {
        float w = W2[k * 64 + h];
        float4 v = *(const float4*)&sh1[k * 16 + grp * 4];
        a2[0] += v.x * w; a2[1] += v.y * w;
        a2[2] += v.z * w; a2[3] += v.w * w;
    }

    // ---- layer 3 + reduction over h ----
    float w3 = W3[h];
    float c[4];
    #pragma unroll
    for (int aa = 0; aa < 4; aa++) c[aa] = fast_tanh(a2[aa]) * w3;
    #pragma unroll
    for (int o = 16; o > 0; o >>= 1) {
        #pragma unroll
        for (int aa = 0; aa < 4; aa++)
            c[aa] += __shfl_down_sync(0xffffffffu, c[aa], o);
    }
    if ((tid & 31) == 0) {
        #pragma unroll
        for (int aa = 0; aa < 4; aa++)
            part[(grp * 2 + half) * 4 + aa] = c[aa];
    }
    __syncthreads();
    if (tid < ATOMS) {
        int g = tid >> 2, aa = tid & 3;
        out[i0 + tid] = part[(g * 2) * 4 + aa] + part[(g * 2 + 1) * 4 + aa]
                      + b3[0];
    }
}

// -------------------------------------------------------------------------
extern "C" void kernel_launch(void* const* d_in, const int* in_sizes, int n_in,
                              void* d_out, int out_size)
{
    const float* pos    = (const float*)d_in[0];
    const float* spec   = (const float*)d_in[1];
    const float* kn_rad = (const float*)d_in[2];
    const float* kn_ang = (const float*)d_in[3];
    const float* rbf_w  = (const float*)d_in[4];
    const float* rbf_b  = (const float*)d_in[5];
    const float* rbf_aw = (const float*)d_in[6];
    const float* rbf_ab = (const float*)d_in[7];
    const float* W1     = (const float*)d_in[8];
    const float* b1     = (const float*)d_in[9];
    const float* W2     = (const float*)d_in[10];
    const float* b2     = (const float*)d_in[11];
    const float* W3     = (const float*)d_in[12];
    const float* b3     = (const float*)d_in[13];

    int N = in_sizes[0] / 3;   // 2048

    feat_kernel<<<N, 128>>>(pos, spec, kn_rad, kn_ang,
                            rbf_w, rbf_b, rbf_aw, rbf_ab, N);
    mlp_kernel<<<N / ATOMS, 256>>>(W1, b1, W2, b2, W3, b3, (float*)d_out, N);
}

// round 4
// speedup vs baseline: 2.7067x; 1.2360x over previous
#include <cuda_runtime.h>
#include <math.h>

#define NG 8
#define NE 4
#define NACC 352          // 32 G + 320 M (before squares)
#define PI_F 3.14159265358979323846f
#define RC_F 6.0f
#define RCA_F 4.0f

// scratch: per-atom feature accumulators (G at [0,32), M at [32,352))
__device__ float g_feat[2048 * NACC];

__device__ __forceinline__ float fast_tanh(float x) {
    float y;
    asm("tanh.approx.f32 %0, %1;" : "=f"(y) : "f"(x));
    return y;
}
__device__ __forceinline__ float fast_sigmoid(float x) {
    return 0.5f * fast_tanh(0.5f * x) + 0.5f;
}

// -------------------------------------------------------------------------
// Kernel 1: descriptors. One block = one atom i, 128 threads.
// 3-phase per 128-j tile:
//   A: distances, ballots, minimal records (rn, inv_r*fc) + spec + monomials
//   B: MUFU basis (sin * gate) redistributed densely over all threads
//   C: accumulate (320 M accs over angular list, 32 G accs over radial list)
// -------------------------------------------------------------------------
__global__ __launch_bounds__(128) void feat_kernel(
    const float* __restrict__ pos,
    const float* __restrict__ spec,
    const float* __restrict__ kn_rad,
    const float* __restrict__ kn_ang,
    const float* __restrict__ rbf_w,
    const float* __restrict__ rbf_b,
    const float* __restrict__ rbf_aw,
    const float* __restrict__ rbf_ab,
    int N)
{
    const int i    = blockIdx.x;
    const int tid  = threadIdx.x;
    const int lane = tid & 31;
    const int w    = tid >> 5;

    __shared__ float  rbuf[128 * 12];   // rad[8] @0, spec[4] @8
    __shared__ float  abuf[128 * 24];   // rad_a[8] @0, ang[10] @8, spec[4] @18
    __shared__ float2 rmin[128];        // {rn, inv_r*fc}
    __shared__ float2 amin[128];        // {rn, inv_r*fca}
    __shared__ int    wc_r[4], wc_a[4];
    __shared__ float  crk[8], cak[8], wr[8], br[8], wa[8], ba[8];

    if (tid < 8) {
        crk[tid] = (PI_F / RC_F)  * (float)(tid + 1) * kn_rad[tid];
        cak[tid] = (PI_F / RCA_F) * (float)(tid + 1) * kn_ang[tid];
        wr[tid]  = rbf_w[tid];  br[tid] = rbf_b[tid];
        wa[tid]  = rbf_aw[tid]; ba[tid] = rbf_ab[tid];
    }

    const float pix = pos[3 * i + 0];
    const float piy = pos[3 * i + 1];
    const float piz = pos[3 * i + 2];
    const float4 si = ((const float4*)spec)[i];

    // ---- M-accumulator decode: a = l*40 + p*4 + e ----
    int oa[3], ob[3], oc[3], fm[3];
    #pragma unroll
    for (int k = 0; k < 3; k++) {
        int a = tid + k * 128;
        if (a < 320) {
            int l = a / 40;
            int r = a - l * 40;
            oa[k] = l;
            ob[k] = 8 + (r >> 2);
            oc[k] = 18 + (r & 3);
            fm[k] = 32 + a;
        }
    }
    const bool has2 = (tid < 64);
    const bool hasG = (tid >= 96);
    const int  gidx = tid - 96;
    const int  gl   = gidx >> 2;
    const int  ge   = 8 + (gidx & 3);

    float acc0 = 0.0f, acc1 = 0.0f, acc2 = 0.0f, gacc = 0.0f;

    for (int tile = 0; tile < N; tile += 128) {
        int  j = tile + tid;
        int  pr = 0, pa = 0;
        float rx = 0.f, ry = 0.f, rz = 0.f, rn = 1.0f, inv_r = 1.0f;
        if (j < N) {
            rx = pix - pos[3 * j + 0];
            ry = piy - pos[3 * j + 1];
            rz = piz - pos[3 * j + 2];
            float d2 = rx * rx + ry * ry + rz * rz + 1e-16f;
            inv_r = rsqrtf(d2);
            rn = d2 * inv_r;
            pr = (j != i) && (rn <= RC_F);
            pa = (j != i) && (rn <= RCA_F);
        }
        unsigned mr = __ballot_sync(0xffffffffu, pr);
        unsigned ma = __ballot_sync(0xffffffffu, pa);
        if (lane == 0) { wc_r[w] = __popc(mr); wc_a[w] = __popc(ma); }
        __syncthreads();                                           // sync1

        int base_r = 0, base_a = 0;
        #pragma unroll
        for (int k = 0; k < 4; k++)
            if (k < w) { base_r += wc_r[k]; base_a += wc_a[k]; }
        int cnt_r = wc_r[0] + wc_r[1] + wc_r[2] + wc_r[3];
        int cnt_a = wc_a[0] + wc_a[1] + wc_a[2] + wc_a[3];

        if (pr) {
            float4 sj = ((const float4*)spec)[j];
            float s0 = si.x * sj.x, s1 = si.y * sj.y;
            float s2 = si.z * sj.z, s3 = si.w * sj.w;

            int slotR = base_r + __popc(mr & ((1u << lane) - 1u));
            float fc = 0.5f * (__cosf((PI_F / RC_F) * rn) + 1.0f);
            rmin[slotR] = make_float2(rn, inv_r * fc);
            float* rr = &rbuf[slotR * 12];
            rr[8] = s0; rr[9] = s1; rr[10] = s2; rr[11] = s3;

            if (pa) {
                int slotA = base_a + __popc(ma & ((1u << lane) - 1u));
                float fca = 0.5f * (__cosf((PI_F / RCA_F) * rn) + 1.0f);
                amin[slotA] = make_float2(rn, inv_r * fca);
                float* rec = &abuf[slotA * 24];
                float ux = rx * inv_r, uy = ry * inv_r, uz = rz * inv_r;
                rec[8]  = 1.0f;
                rec[9]  = uz;
                rec[10] = uy;
                rec[11] = ux;
                rec[12] = uz * uz;
                rec[13] = uy * uz;
                rec[14] = uy * uy;
                rec[15] = ux * uz;
                rec[16] = ux * uy;
                rec[17] = ux * ux;
                rec[18] = s0; rec[19] = s1; rec[20] = s2; rec[21] = s3;
            }
        }
        __syncthreads();                                           // sync2

        // ---- phase B: dense MUFU basis fill ----
        for (int idx = tid; idx < cnt_r * 8; idx += 128) {
            int s = idx >> 3, n = idx & 7;
            float2 m = rmin[s];
            rbuf[s * 12 + n] = __sinf(crk[n] * m.x) * m.y
                             * fast_sigmoid(fmaf(m.x, wr[n], br[n]));
        }
        for (int idx = tid; idx < cnt_a * 8; idx += 128) {
            int s = idx >> 3, n = idx & 7;
            float2 m = amin[s];
            abuf[s * 24 + n] = __sinf(cak[n] * m.x) * m.y
                             * fast_sigmoid(fmaf(m.x, wa[n], ba[n]));
        }
        __syncthreads();                                           // sync3

        // ---- phase C: accumulate ----
        #pragma unroll 2
        for (int s = 0; s < cnt_a; s++) {
            const float* rec = &abuf[s * 24];
            acc0 += rec[oa[0]] * rec[ob[0]] * rec[oc[0]];
            acc1 += rec[oa[1]] * rec[ob[1]] * rec[oc[1]];
            if (has2) acc2 += rec[oa[2]] * rec[ob[2]] * rec[oc[2]];
        }
        if (hasG) {
            #pragma unroll 4
            for (int s = 0; s < cnt_r; s++) {
                const float* rec = &rbuf[s * 12];
                gacc = fmaf(rec[gl], rec[ge], gacc);
            }
        }
        // next tile's shared writes are gated by its sync1
    }

    float* fo = &g_feat[i * NACC];
    fo[fm[0]] = acc0;
    fo[fm[1]] = acc1;
    if (has2) fo[fm[2]] = acc2;
    if (hasG) fo[gidx]  = gacc;
}

// -------------------------------------------------------------------------
// Kernel 2: per-atom MLP (672 -> 64 tanh -> 64 tanh -> 1), 8 atoms/block,
// 256 threads (h = tid&63, grp = tid>>6 owns atoms 2*grp, 2*grp+1).
// W1 staged through smem: G rows once; M rows in 8 paired tiles of 40
// (w row f and squared-row f+320), register-prefetch double buffering.
// -------------------------------------------------------------------------
#define MATOMS 8
__global__ __launch_bounds__(256) void mlp_kernel(
    const float* __restrict__ W1, const float* __restrict__ b1,
    const float* __restrict__ W2, const float* __restrict__ b2,
    const float* __restrict__ W3, const float* __restrict__ b3,
    float* __restrict__ out, int N)
{
    const int i0   = blockIdx.x * MATOMS;
    const int tid  = threadIdx.x;
    const int h    = tid & 63;
    const int grp  = tid >> 6;          // 0..3
    const int wid  = tid >> 5;          // 0..7

    __shared__ float sfr[NACC * MATOMS];   // [f][a] stride 8   11.0 KB
    __shared__ float wg[32 * 64];          // G rows             8 KB
    __shared__ float wt[80 * 64];          // tile: w[0:40), wsq[40:80)  20 KB
    __shared__ float sh1[64 * MATOMS];     // [k][a]             2 KB
    __shared__ float part[8][2];

    for (int idx = tid; idx < NACC * MATOMS; idx += 256) {
        int a = idx / NACC;
        int f = idx - a * NACC;
        sfr[f * MATOMS + a] = g_feat[(i0 + a) * NACC + f];
    }
    // stage G rows [0,32): 512 float4
    {
        const float4* src = (const float4*)W1;
        float4* dst = (float4*)wg;
        dst[tid] = src[tid];
        dst[tid + 256] = src[tid + 256];
    }
    // stage tile 0: rows [32,72) and [352,392): 1280 float4
    {
        const float4* s1 = (const float4*)(W1 + 32 * 64);
        const float4* s2 = (const float4*)(W1 + 352 * 64);
        float4* dst = (float4*)wt;
        #pragma unroll
        for (int k = 0; k < 5; k++) {
            int g = tid + 256 * k;
            dst[g] = (g < 640) ? s1[g] : s2[g - 640];
        }
    }
    __syncthreads();

    float acc0 = 0.0f, acc1 = 0.0f;
    // ---- layer 1, G block ----
    #pragma unroll 8
    for (int f = 0; f < 32; f++) {
        float ww = wg[f * 64 + h];
        float2 v = *(const float2*)&sfr[f * MATOMS + grp * 2];
        acc0 = fmaf(v.x, ww, acc0);
        acc1 = fmaf(v.y, ww, acc1);
    }
    // ---- layer 1, M tiles (8 x 40 rows, fused square weights) ----
    for (int t = 0; t < 8; t++) {
        float4 pre[5];
        if (t < 7) {
            const float4* s1 = (const float4*)(W1 + (72 + 40 * t) * 64);
            const float4* s2 = (const float4*)(W1 + (392 + 40 * t) * 64);
            #pragma unroll
            for (int k = 0; k < 5; k++) {
                int g = tid + 256 * k;
                pre[k] = (g < 640) ? s1[g] : s2[g - 640];
            }
        }
        const int fb = (32 + 40 * t) * MATOMS + grp * 2;
        #pragma unroll 8
        for (int f = 0; f < 40; f++) {
            float ww  = wt[f * 64 + h];
            float ws  = wt[(40 + f) * 64 + h];
            float2 v  = *(const float2*)&sfr[fb + f * MATOMS];
            float t0 = fmaf(v.x, ws, ww);
            float t1 = fmaf(v.y, ws, ww);
            acc0 = fmaf(v.x, t0, acc0);
            acc1 = fmaf(v.y, t1, acc1);
        }
        __syncthreads();
        if (t < 7) {
            float4* dst = (float4*)wt;
            #pragma unroll
            for (int k = 0; k < 5; k++)
                dst[tid + 256 * k] = pre[k];
            __syncthreads();
        }
    }
    {
        float bb = b1[h];
        sh1[h * MATOMS + grp * 2 + 0] = fast_tanh(acc0 + bb);
        sh1[h * MATOMS + grp * 2 + 1] = fast_tanh(acc1 + bb);
    }
    __syncthreads();

    // ---- layer 2 ----
    float s0, s1v;
    {
        float bb = b2[h];
        s0 = bb; s1v = bb;
    }
    #pragma unroll 8
    for (int k = 0; k < 64; k++) {
        float ww = W2[k * 64 + h];
        float2 v = *(const float2*)&sh1[k * MATOMS + grp * 2];
        s0  = fmaf(v.x, ww, s0);
        s1v = fmaf(v.y, ww, s1v);
    }

    // ---- layer 3 + reduction over h (each grp spans warps 2g, 2g+1) ----
    float w3 = W3[h];
    float c0 = fast_tanh(s0)  * w3;
    float c1 = fast_tanh(s1v) * w3;
    #pragma unroll
    for (int o = 16; o > 0; o >>= 1) {
        c0 += __shfl_down_sync(0xffffffffu, c0, o);
        c1 += __shfl_down_sync(0xffffffffu, c1, o);
    }
    if ((tid & 31) == 0) { part[wid][0] = c0; part[wid][1] = c1; }
    __syncthreads();
    if (tid < MATOMS) {
        int g = tid >> 1, sub = tid & 1;
        out[i0 + tid] = part[2 * g][sub] + part[2 * g + 1][sub] + b3[0];
    }
}

// -------------------------------------------------------------------------
extern "C" void kernel_launch(void* const* d_in, const int* in_sizes, int n_in,
                              void* d_out, int out_size)
{
    const float* pos    = (const float*)d_in[0];
    const float* spec   = (const float*)d_in[1];
    const float* kn_rad = (const float*)d_in[2];
    const float* kn_ang = (const float*)d_in[3];
    const float* rbf_w  = (const float*)d_in[4];
    const float* rbf_b  = (const float*)d_in[5];
    const float* rbf_aw = (const float*)d_in[6];
    const float* rbf_ab = (const float*)d_in[7];
    const float* W1     = (const float*)d_in[8];
    const float* b1     = (const float*)d_in[9];
    const float* W2     = (const float*)d_in[10];
    const float* b2     = (const float*)d_in[11];
    const float* W3     = (const float*)d_in[12];
    const float* b3     = (const float*)d_in[13];

    int N = in_sizes[0] / 3;   // 2048

    feat_kernel<<<N, 128>>>(pos, spec, kn_rad, kn_ang,
                            rbf_w, rbf_b, rbf_aw, rbf_ab, N);
    mlp_kernel<<<N / MATOMS, 256>>>(W1, b1, W2, b2, W3, b3, (float*)d_out, N);
}

// round 5
// speedup vs baseline: 3.2170x; 1.1885x over previous
#include <cuda_runtime.h>

#define NACC 352          // 32 G + 320 M (before squares)
#define PI_F 3.14159265358979323846f

// scratch: [half][atom][feature] partial accumulators
__device__ float g_feat[2 * 2048 * NACC];

__device__ __forceinline__ float fast_tanh(float x) {
    float y;
    asm("tanh.approx.f32 %0, %1;" : "=f"(y) : "f"(x));
    return y;
}
__device__ __forceinline__ float fast_sigmoid(float x) {
    return 0.5f * fast_tanh(0.5f * x) + 0.5f;
}
__device__ __forceinline__ unsigned smem_u32(const void* p) {
    return (unsigned)__cvta_generic_to_shared(p);
}
#define CP_ASYNC16(dst, src) \
    asm volatile("cp.async.cg.shared.global [%0], [%1], 16;\n" \
                 :: "r"(dst), "l"(src))
#define CP_COMMIT() asm volatile("cp.async.commit_group;\n")
template <int NLeft>
__device__ __forceinline__ void cp_wait() {
    asm volatile("cp.async.wait_group %0;\n" :: "n"(NLeft));
}

// -------------------------------------------------------------------------
// Kernel 1: descriptors.  One WARP per (atom, j-half).  No block barriers.
// Lane = (l, e) with l = lane>>2, e = lane&3.  Registers hold:
//   gacc        : G[l,e]
//   macc[0..9]  : M[l, p, e] for p = 0..9
// Per 32-j chunk: distances + ballot; iterate survivors via ffs, broadcast
// the survivor's scalars with shuffles, each lane computes its basis value
// (1 sin + 1 tanh per cutoff, lane-parallel over l) and updates registers.
// -------------------------------------------------------------------------
__global__ __launch_bounds__(256) void feat_kernel(
    const float* __restrict__ pos,
    const float* __restrict__ spec,
    const float* __restrict__ kn_rad,
    const float* __restrict__ kn_ang,
    const float* __restrict__ rbf_w,
    const float* __restrict__ rbf_b,
    const float* __restrict__ rbf_aw,
    const float* __restrict__ rbf_ab,
    int N)
{
    const int wid  = threadIdx.x >> 5;
    const int lane = threadIdx.x & 31;
    const int g    = blockIdx.x * 8 + wid;   // global warp id
    const int i    = g >> 1;                 // atom
    const int half = g & 1;                  // j-half
    const int myl  = lane >> 2;
    const int mye  = lane & 3;

    const float crk = (PI_F / 6.0f) * (float)(myl + 1) * kn_rad[myl];
    const float cak = (PI_F / 4.0f) * (float)(myl + 1) * kn_ang[myl];
    const float wr = rbf_w[myl],  br = rbf_b[myl];
    const float wa = rbf_aw[myl], ba = rbf_ab[myl];

    const float pix = pos[3 * i + 0];
    const float piy = pos[3 * i + 1];
    const float piz = pos[3 * i + 2];
    const float4 si = ((const float4*)spec)[i];

    float gacc = 0.0f;
    float macc[10];
    #pragma unroll
    for (int p = 0; p < 10; p++) macc[p] = 0.0f;

    const int jbeg = half * (N >> 1);
    const int jend = jbeg + (N >> 1);

    for (int j0 = jbeg; j0 < jend; j0 += 32) {
        int j = j0 + lane;
        float rx = pix - pos[3 * j + 0];
        float ry = piy - pos[3 * j + 1];
        float rz = piz - pos[3 * j + 2];
        float d2 = fmaf(rx, rx, fmaf(ry, ry, rz * rz)) + 1e-16f;
        float inv = rsqrtf(d2);
        float rn = d2 * inv;
        bool pr = (j != i) && (rn <= 6.0f);
        bool pa = pr && (rn <= 4.0f);
        unsigned mr = __ballot_sync(0xffffffffu, pr);
        unsigned ma = __ballot_sync(0xffffffffu, pa);

        float p0 = 0.f, p1 = 0.f, p2 = 0.f, p3 = 0.f;
        if (pr) {
            float4 sj = ((const float4*)spec)[j];
            p0 = si.x * sj.x; p1 = si.y * sj.y;
            p2 = si.z * sj.z; p3 = si.w * sj.w;
        }

        while (mr) {
            int s = __ffs(mr) - 1;
            mr &= mr - 1;
            float srn  = __shfl_sync(0xffffffffu, rn,  s);
            float sinv = __shfl_sync(0xffffffffu, inv, s);
            float v0 = __shfl_sync(0xffffffffu, p0, s);
            float v1 = __shfl_sync(0xffffffffu, p1, s);
            float v2 = __shfl_sync(0xffffffffu, p2, s);
            float v3 = __shfl_sync(0xffffffffu, p3, s);
            float sp = (mye == 0) ? v0 : (mye == 1) ? v1
                     : (mye == 2) ? v2 : v3;

            float fc   = 0.5f * (__cosf((PI_F / 6.0f) * srn) + 1.0f);
            float radl = __sinf(crk * srn) * (sinv * fc)
                       * fast_sigmoid(fmaf(srn, wr, br));
            gacc = fmaf(radl, sp, gacc);

            if ((ma >> s) & 1u) {
                float sux = __shfl_sync(0xffffffffu, rx, s) * sinv;
                float suy = __shfl_sync(0xffffffffu, ry, s) * sinv;
                float suz = __shfl_sync(0xffffffffu, rz, s) * sinv;
                float fca = 0.5f * (__cosf((PI_F / 4.0f) * srn) + 1.0f);
                float ral = __sinf(cak * srn) * (sinv * fca)
                          * fast_sigmoid(fmaf(srn, wa, ba));
                float w  = ral * sp;
                float wz = w * suz, wy = w * suy, wx = w * sux;
                macc[0] += w;
                macc[1] += wz;
                macc[2] += wy;
                macc[3] += wx;
                macc[4] = fmaf(wz, suz, macc[4]);   // uz^2
                macc[5] = fmaf(wz, suy, macc[5]);   // uy*uz
                macc[6] = fmaf(wy, suy, macc[6]);   // uy^2
                macc[7] = fmaf(wz, sux, macc[7]);   // ux*uz
                macc[8] = fmaf(wy, sux, macc[8]);   // ux*uy
                macc[9] = fmaf(wx, sux, macc[9]);   // ux^2
            }
        }
    }

    float* fo = &g_feat[(half * 2048 + i) * NACC];
    fo[myl * 4 + mye] = gacc;
    #pragma unroll
    for (int p = 0; p < 10; p++)
        fo[32 + myl * 40 + p * 4 + mye] = macc[p];
}

// -------------------------------------------------------------------------
// Kernel 2: per-atom MLP (672 -> 64 tanh -> 64 tanh -> 1), 8 atoms/block,
// 256 threads.  W1 staged via cp.async: G rows (32) once; M rows in 16
// double-buffered tiles of 20 paired rows (w row f and square-row f+320).
// Static smem ~41.5 KB -> ~5 resident blocks/SM.
// -------------------------------------------------------------------------
#define MATOMS 8
__global__ __launch_bounds__(256) void mlp_kernel(
    const float* __restrict__ W1, const float* __restrict__ b1,
    const float* __restrict__ W2, const float* __restrict__ b2,
    const float* __restrict__ W3, const float* __restrict__ b3,
    float* __restrict__ out, int N)
{
    const int i0   = blockIdx.x * MATOMS;
    const int tid  = threadIdx.x;
    const int h    = tid & 63;
    const int grp  = tid >> 6;          // 0..3 -> atoms 2*grp, 2*grp+1
    const int wid  = tid >> 5;          // 0..7

    __shared__ float sfr[NACC * MATOMS];    // [f][a]           11.0 KB
    __shared__ float wg[32 * 64];           // G rows            8.0 KB
    __shared__ float wt[2][40 * 64];        // w[0:20), wsq[20:40)  20.5 KB
    __shared__ float sh1[64 * MATOMS];      //                   2.0 KB
    __shared__ float part[8][2];

    // ---- async stage G rows (group 0) ----
    {
        unsigned d = smem_u32(wg);
        const float4* s = (const float4*)W1;
        CP_ASYNC16(d + tid * 16,          (const void*)(s + tid));
        CP_ASYNC16(d + (tid + 256) * 16,  (const void*)(s + tid + 256));
        CP_COMMIT();
    }
    // ---- async stage M tile 0 (group 1): rows [32,52) + [352,372) ----
    {
        unsigned d = smem_u32(wt[0]);
        const float4* s1 = (const float4*)(W1 + 32 * 64);
        const float4* s2 = (const float4*)(W1 + 352 * 64);
        #pragma unroll
        for (int k = 0; k < 3; k++) {
            int q = tid + 256 * k;
            if (q < 640)
                CP_ASYNC16(d + q * 16,
                           (const void*)(q < 320 ? s1 + q : s2 + (q - 320)));
        }
        CP_COMMIT();
    }

    // ---- load features, summing the two halves ----
    for (int idx = tid; idx < NACC * MATOMS; idx += 256) {
        int a = idx / NACC;
        int f = idx - a * NACC;
        sfr[f * MATOMS + a] = g_feat[(i0 + a) * NACC + f]
                            + g_feat[(2048 + i0 + a) * NACC + f];
    }

    cp_wait<1>();          // G tile complete
    __syncthreads();

    float acc0 = 0.0f, acc1 = 0.0f;
    // ---- layer 1, G block ----
    #pragma unroll 8
    for (int f = 0; f < 32; f++) {
        float ww = wg[f * 64 + h];
        float2 v = *(const float2*)&sfr[f * MATOMS + grp * 2];
        acc0 = fmaf(v.x, ww, acc0);
        acc1 = fmaf(v.y, ww, acc1);
    }

    // ---- layer 1, M tiles: 16 tiles x 20 paired rows ----
    for (int t = 0; t < 16; t++) {
        if (t < 15) {   // prefetch tile t+1 into the other buffer
            unsigned d = smem_u32(wt[(t + 1) & 1]);
            const float4* s1 = (const float4*)(W1 + (52 + 20 * t) * 64);
            const float4* s2 = (const float4*)(W1 + (372 + 20 * t) * 64);
            #pragma unroll
            for (int k = 0; k < 3; k++) {
                int q = tid + 256 * k;
                if (q < 640)
                    CP_ASYNC16(d + q * 16,
                               (const void*)(q < 320 ? s1 + q : s2 + (q - 320)));
            }
            CP_COMMIT();
            cp_wait<1>();      // tile t complete (t+1 still in flight)
        } else {
            cp_wait<0>();
        }
        __syncthreads();       // tile t visible to all threads

        const float* wb = wt[t & 1];
        const int fb = (32 + 20 * t) * MATOMS + grp * 2;
        #pragma unroll 10
        for (int f = 0; f < 20; f++) {
            float ww = wb[f * 64 + h];
            float ws = wb[(20 + f) * 64 + h];
            float2 v = *(const float2*)&sfr[fb + f * MATOMS];
            float t0 = fmaf(v.x, ws, ww);
            float t1 = fmaf(v.y, ws, ww);
            acc0 = fmaf(v.x, t0, acc0);
            acc1 = fmaf(v.y, t1, acc1);
        }
        __syncthreads();       // all readers done before buffer reuse
    }

    {
        float bb = b1[h];
        sh1[h * MATOMS + grp * 2 + 0] = fast_tanh(acc0 + bb);
        sh1[h * MATOMS + grp * 2 + 1] = fast_tanh(acc1 + bb);
    }
    __syncthreads();

    // ---- layer 2 ----
    float s0, s1v;
    {
        float bb = b2[h];
        s0 = bb; s1v = bb;
    }
    #pragma unroll 8
    for (int k = 0; k < 64; k++) {
        float ww = W2[k * 64 + h];
        float2 v = *(const float2*)&sh1[k * MATOMS + grp * 2];
        s0  = fmaf(v.x, ww, s0);
        s1v = fmaf(v.y, ww, s1v);
    }

    // ---- layer 3 + warp reduction over h ----
    float w3 = W3[h];
    float c0 = fast_tanh(s0)  * w3;
    float c1 = fast_tanh(s1v) * w3;
    #pragma unroll
    for (int o = 16; o > 0; o >>= 1) {
        c0 += __shfl_down_sync(0xffffffffu, c0, o);
        c1 += __shfl_down_sync(0xffffffffu, c1, o);
    }
    if ((tid & 31) == 0) { part[wid][0] = c0; part[wid][1] = c1; }
    __syncthreads();
    if (tid < MATOMS) {
        int gg = tid >> 1, sub = tid & 1;
        out[i0 + tid] = part[2 * gg][sub] + part[2 * gg + 1][sub] + b3[0];
    }
}

// -------------------------------------------------------------------------
extern "C" void kernel_launch(void* const* d_in, const int* in_sizes, int n_in,
                              void* d_out, int out_size)
{
    const float* pos    = (const float*)d_in[0];
    const float* spec   = (const float*)d_in[1];
    const float* kn_rad = (const float*)d_in[2];
    const float* kn_ang = (const float*)d_in[3];
    const float* rbf_w  = (const float*)d_in[4];
    const float* rbf_b  = (const float*)d_in[5];
    const float* rbf_aw = (const float*)d_in[6];
    const float* rbf_ab = (const float*)d_in[7];
    const float* W1     = (const float*)d_in[8];
    const float* b1     = (const float*)d_in[9];
    const float* W2     = (const float*)d_in[10];
    const float* b2     = (const float*)d_in[11];
    const float* W3     = (const float*)d_in[12];
    const float* b3     = (const float*)d_in[13];

    int N = in_sizes[0] / 3;   // 2048

    feat_kernel<<<2 * N / 8, 256>>>(pos, spec, kn_rad, kn_ang,
                                    rbf_w, rbf_b, rbf_aw, rbf_ab, N);
    mlp_kernel<<<N / MATOMS, 256>>>(W1, b1, W2, b2, W3, b3, (float*)d_out, N);
}

// round 6
// speedup vs baseline: 3.3360x; 1.0370x over previous
#include <cuda_runtime.h>

#define NACC 352          // 32 G + 320 M (before squares)
#define PI_F 3.14159265358979323846f
#define C6   (PI_F / 6.0f)
#define C4   (PI_F / 4.0f)

// scratch: [half][atom][feature] partial accumulators + hidden layer
__device__ float g_feat[2 * 2048 * NACC];
__device__ float g_h1[2048 * 64];

__device__ __forceinline__ float fast_tanh(float x) {
    float y;
    asm("tanh.approx.f32 %0, %1;" : "=f"(y) : "f"(x));
    return y;
}
__device__ __forceinline__ float fast_sigmoid(float x) {
    return 0.5f * fast_tanh(0.5f * x) + 0.5f;
}

// -------------------------------------------------------------------------
// Kernel 1: descriptors.  One WARP per (atom, j-half); 8 warps/block.
// Lane = (l, e), l = lane>>2, e = lane&3.  Registers hold G[l,e] + M[l,p,e].
// Per 32-j chunk: distances from smem-staged positions, ballot, survivors
// write a 12-float record into a warp-private smem slab (angular-sorted
// first), then a uniform loop reads records via broadcast LDS and updates
// register accumulators.  s_i factor applied once at the end.
// Record layout (floats): [0..3]={ux,uy,uz,rn} [4]=inv_r [5..8]=s_j[0..3]
// -------------------------------------------------------------------------
__global__ __launch_bounds__(256) void feat_kernel(
    const float* __restrict__ pos,
    const float* __restrict__ spec,
    const float* __restrict__ kn_rad,
    const float* __restrict__ kn_ang,
    const float* __restrict__ rbf_w,
    const float* __restrict__ rbf_b,
    const float* __restrict__ rbf_aw,
    const float* __restrict__ rbf_ab,
    int N)
{
    const int tid  = threadIdx.x;
    const int wid  = tid >> 5;
    const int lane = tid & 31;
    const int g    = blockIdx.x * 8 + wid;
    const int i    = g >> 1;
    const int half = g & 1;
    const int myl  = lane >> 2;
    const int mye  = lane & 3;

    __shared__ float spos[2048 * 3];       // 24 KB
    __shared__ float rec[8][32 * 12];      // 12 KB, warp-private slabs

    for (int idx = tid; idx < 3 * N; idx += 256) spos[idx] = pos[idx];
    __syncthreads();

    const float crk = C6 * (float)(myl + 1) * kn_rad[myl];
    const float cak = C4 * (float)(myl + 1) * kn_ang[myl];
    const float wr = rbf_w[myl],  br = rbf_b[myl];
    const float wa = rbf_aw[myl], ba = rbf_ab[myl];

    const float pix = spos[3 * i + 0];
    const float piy = spos[3 * i + 1];
    const float piz = spos[3 * i + 2];
    const float4 si = ((const float4*)spec)[i];
    const float sie = (mye == 0) ? si.x : (mye == 1) ? si.y
                    : (mye == 2) ? si.z : si.w;

    float gacc = 0.0f;
    float macc[10];
    #pragma unroll
    for (int p = 0; p < 10; p++) macc[p] = 0.0f;

    float* slab = &rec[wid][0];
    const unsigned ltm = (1u << lane) - 1u;
    const int jbeg = half * (N >> 1);
    const int jend = jbeg + (N >> 1);

    for (int j0 = jbeg; j0 < jend; j0 += 32) {
        int j = j0 + lane;
        float rx = pix - spos[3 * j + 0];
        float ry = piy - spos[3 * j + 1];
        float rz = piz - spos[3 * j + 2];
        float d2 = fmaf(rx, rx, fmaf(ry, ry, rz * rz)) + 1e-16f;
        float inv = rsqrtf(d2);
        float rn = d2 * inv;
        bool pr = (j != i) && (rn <= 6.0f);
        bool pa = pr && (rn <= 4.0f);
        unsigned mr = __ballot_sync(0xffffffffu, pr);
        unsigned ma = __ballot_sync(0xffffffffu, pa);
        int cnt_a = __popc(ma);
        int cnt   = __popc(mr);

        if (pr) {
            int slot = pa ? __popc(ma & ltm)
                          : cnt_a + __popc((mr & ~ma) & ltm);
            float4 sj = ((const float4*)spec)[j];
            float* rp = slab + slot * 12;
            ((float4*)rp)[0] = make_float4(rx * inv, ry * inv, rz * inv, rn);
            ((float4*)rp)[1] = make_float4(inv, sj.x, sj.y, sj.z);
            rp[8] = sj.w;
        }
        __syncwarp();

        // angular survivors: full update
        for (int s = 0; s < cnt_a; s++) {
            const float* rp = slab + s * 12;
            float4 q   = ((const float4*)rp)[0];   // ux,uy,uz,rn
            float  riv = rp[4];
            float  spj = rp[5 + mye];
            float  srn = q.w;
            float fc   = 0.5f * (__cosf(C6 * srn) + 1.0f);
            float radl = __sinf(crk * srn) * (riv * fc)
                       * fast_sigmoid(fmaf(srn, wr, br));
            gacc = fmaf(radl, spj, gacc);

            float fca = 0.5f * (__cosf(C4 * srn) + 1.0f);
            float ral = __sinf(cak * srn) * (riv * fca)
                      * fast_sigmoid(fmaf(srn, wa, ba));
            float w  = ral * spj;
            float wx = w * q.x, wy = w * q.y, wz = w * q.z;
            macc[0] += w;
            macc[1] += wz;
            macc[2] += wy;
            macc[3] += wx;
            macc[4] = fmaf(wz, q.z, macc[4]);
            macc[5] = fmaf(wz, q.y, macc[5]);
            macc[6] = fmaf(wy, q.y, macc[6]);
            macc[7] = fmaf(wz, q.x, macc[7]);
            macc[8] = fmaf(wy, q.x, macc[8]);
            macc[9] = fmaf(wx, q.x, macc[9]);
        }
        // radial-only survivors
        for (int s = cnt_a; s < cnt; s++) {
            const float* rp = slab + s * 12;
            float srn = rp[3];
            float riv = rp[4];
            float spj = rp[5 + mye];
            float fc   = 0.5f * (__cosf(C6 * srn) + 1.0f);
            float radl = __sinf(crk * srn) * (riv * fc)
                       * fast_sigmoid(fmaf(srn, wr, br));
            gacc = fmaf(radl, spj, gacc);
        }
        __syncwarp();
    }

    float* fo = &g_feat[(half * 2048 + i) * NACC];
    fo[myl * 4 + mye] = gacc * sie;
    #pragma unroll
    for (int p = 0; p < 10; p++)
        fo[32 + myl * 40 + p * 4 + mye] = macc[p] * sie;
}

// -------------------------------------------------------------------------
// Kernel 2a: MLP layer 1 (672 -> 64, tanh).  4 atoms per thread.
// Block = 128 threads = 32 hidden (h-half) x 4 groups of 4 atoms.
// grid = (2048/16 atom-groups) x (2 h-halves) = 256 blocks.
// Weights straight from L1 (coalesced 128B rows); no inner barriers.
// -------------------------------------------------------------------------
__global__ __launch_bounds__(128) void mlp1_kernel(
    const float* __restrict__ W1, const float* __restrict__ b1, int N)
{
    const int group = blockIdx.x >> 1;     // atom group of 16
    const int hh    = blockIdx.x & 1;
    const int tid   = threadIdx.x;
    const int h     = hh * 32 + (tid & 31);
    const int grp   = tid >> 5;            // 0..3 -> 4 atoms each
    const int a0    = group * 16;

    __shared__ float sfr[NACC * 16];       // [f][a], 22.5 KB

    for (int idx = tid; idx < NACC * 16; idx += 128) {
        int a = idx / NACC;
        int f = idx - a * NACC;
        sfr[f * 16 + a] = g_feat[(a0 + a) * NACC + f]
                        + g_feat[(2048 + a0 + a) * NACC + f];
    }
    __syncthreads();

    float acc0 = 0.f, acc1 = 0.f, acc2 = 0.f, acc3 = 0.f;

    // G rows [0,32)
    #pragma unroll 8
    for (int f = 0; f < 32; f++) {
        float w = W1[f * 64 + h];
        float4 v = *(const float4*)&sfr[f * 16 + grp * 4];
        acc0 = fmaf(v.x, w, acc0);
        acc1 = fmaf(v.y, w, acc1);
        acc2 = fmaf(v.z, w, acc2);
        acc3 = fmaf(v.w, w, acc3);
    }
    // M rows [32,352): fused linear + square weights
    #pragma unroll 8
    for (int f = 32; f < NACC; f++) {
        float w  = W1[f * 64 + h];
        float ws = W1[(f + 320) * 64 + h];
        float4 v = *(const float4*)&sfr[f * 16 + grp * 4];
        float t0 = fmaf(v.x, ws, w);
        float t1 = fmaf(v.y, ws, w);
        float t2 = fmaf(v.z, ws, w);
        float t3 = fmaf(v.w, ws, w);
        acc0 = fmaf(v.x, t0, acc0);
        acc1 = fmaf(v.y, t1, acc1);
        acc2 = fmaf(v.z, t2, acc2);
        acc3 = fmaf(v.w, t3, acc3);
    }

    float bb = b1[h];
    int a = a0 + grp * 4;
    g_h1[(a + 0) * 64 + h] = fast_tanh(acc0 + bb);
    g_h1[(a + 1) * 64 + h] = fast_tanh(acc1 + bb);
    g_h1[(a + 2) * 64 + h] = fast_tanh(acc2 + bb);
    g_h1[(a + 3) * 64 + h] = fast_tanh(acc3 + bb);
}

// -------------------------------------------------------------------------
// Kernel 2b: MLP layers 2+3 (64 -> 64 tanh -> 1).  8 atoms/block.
// 256 threads: h = tid&63, grp = tid>>6 handles atoms 2*grp, 2*grp+1.
// -------------------------------------------------------------------------
__global__ __launch_bounds__(256) void mlp2_kernel(
    const float* __restrict__ W2, const float* __restrict__ b2,
    const float* __restrict__ W3, const float* __restrict__ b3,
    float* __restrict__ out, int N)
{
    const int i0   = blockIdx.x * 8;
    const int tid  = threadIdx.x;
    const int h    = tid & 63;
    const int grp  = tid >> 6;
    const int wid  = tid >> 5;

    __shared__ float sh1[64 * 8];
    __shared__ float part[8][2];

    for (int idx = tid; idx < 512; idx += 256) {
        int a = idx >> 6, k = idx & 63;
        sh1[k * 8 + a] = g_h1[(i0 + a) * 64 + k];
    }
    __syncthreads();

    float bb = b2[h];
    float s0 = bb, s1 = bb;
    #pragma unroll 8
    for (int k = 0; k < 64; k++) {
        float w = W2[k * 64 + h];
        float2 v = *(const float2*)&sh1[k * 8 + grp * 2];
        s0 = fmaf(v.x, w, s0);
        s1 = fmaf(v.y, w, s1);
    }

    float w3 = W3[h];
    float c0 = fast_tanh(s0) * w3;
    float c1 = fast_tanh(s1) * w3;
    #pragma unroll
    for (int o = 16; o > 0; o >>= 1) {
        c0 += __shfl_down_sync(0xffffffffu, c0, o);
        c1 += __shfl_down_sync(0xffffffffu, c1, o);
    }
    if ((tid & 31) == 0) { part[wid][0] = c0; part[wid][1] = c1; }
    __syncthreads();
    if (tid < 8) {
        int gg = tid >> 1, sub = tid & 1;
        out[i0 + tid] = part[2 * gg][sub] + part[2 * gg + 1][sub] + b3[0];
    }
}

// -------------------------------------------------------------------------
extern "C" void kernel_launch(void* const* d_in, const int* in_sizes, int n_in,
                              void* d_out, int out_size)
{
    const float* pos    = (const float*)d_in[0];
    const float* spec   = (const float*)d_in[1];
    const float* kn_rad = (const float*)d_in[2];
    const float* kn_ang = (const float*)d_in[3];
    const float* rbf_w  = (const float*)d_in[4];
    const float* rbf_b  = (const float*)d_in[5];
    const float* rbf_aw = (const float*)d_in[6];
    const float* rbf_ab = (const float*)d_in[7];
    const float* W1     = (const float*)d_in[8];
    const float* b1     = (const float*)d_in[9];
    const float* W2     = (const float*)d_in[10];
    const float* b2     = (const float*)d_in[11];
    const float* W3     = (const float*)d_in[12];
    const float* b3     = (const float*)d_in[13];

    int N = in_sizes[0] / 3;   // 2048

    feat_kernel<<<2 * N / 8, 256>>>(pos, spec, kn_rad, kn_ang,
                                    rbf_w, rbf_b, rbf_aw, rbf_ab, N);
    mlp1_kernel<<<(N / 16) * 2, 128>>>(W1, b1, N);
    mlp2_kernel<<<N / 8, 256>>>(W2, b2, W3, b3, (float*)d_out, N);
}